// round 4
// baseline (speedup 1.0000x reference)
#include <cuda_runtime.h>
#include <math.h>

#define S 256
#define NB 128
#define D 256
#define L 8
#define EPS 1e-8f

typedef unsigned long long ull;

#define MUL2(d_, a_, b_) asm("mul.rn.f32x2 %0, %1, %2;" : "=l"(d_) : "l"(a_), "l"(b_))
#define ADD2(d_, a_, b_) asm("add.rn.f32x2 %0, %1, %2;" : "=l"(d_) : "l"(a_), "l"(b_))
#define FMA2(d_, a_, b_, c_) asm("fma.rn.f32x2 %0, %1, %2, %3;" : "=l"(d_) : "l"(a_), "l"(b_), "l"(c_))
#define PACK2(d_, x_) asm("mov.b64 %0, {%1, %1};" : "=l"(d_) : "f"(x_))
#define UNPACK2(lo_, hi_, p_) asm("mov.b64 {%0, %1}, %2;" : "=f"(lo_), "=f"(hi_) : "l"(p_))

// ---- scratch (static device memory; no allocations anywhere) ----
__device__ __align__(16) float g_w2[6][L][D];        // W[0..5]^2
// norm slots: 0-7 full(W0/W1), 8-15 maxpool(W2/W3), 16-23 W4, 24-31 W5, 32 unweighted
__device__ __align__(16) float g_np[2][S][NB][33];   // [dir][pos][b][slot]
__device__ __align__(16) float g_nq[2][S][NB][33];
__device__ __align__(16) float g_alpha[2][NB][S][S]; // [dir][b][s][t]
__device__ __align__(16) float g_rowsum[2][NB][S];
__device__ __align__(16) int   g_amax[2][NB][S];
__device__ __align__(16) float g_h[2][NB][S][D];     // h_mean (already divided by rowsum)

// ---------------- K0: W^2 ----------------
__global__ void k_w2(const float* __restrict__ W){
  int i = blockIdx.x*blockDim.x + threadIdx.x;
  if (i < 6*L*D){ float w = W[i]; (&g_w2[0][0][0])[i] = w*w; }
}

// ---------------- K1: all weighted norms ----------------
__global__ void __launch_bounds__(128) k_norms(const float* __restrict__ P,
                                               const float* __restrict__ Q){
  __shared__ float sw[6*L*D];
  int tid = threadIdx.x;
  for (int i=tid; i<6*L*D; i+=128) sw[i] = (&g_w2[0][0][0])[i];
  __syncthreads();
  int warp = tid>>5, lane = tid&31;
  int tensor = warp>>1, dir = warp&1;
  const float* X = tensor ? Q : P;
  float* dst = tensor ? &g_nq[0][0][0][0] : &g_np[0][0][0][0];
  int wrow0 = dir, wrow1 = 2+dir;
  for (int it=0; it<16; it++){
    int r = blockIdx.x*16 + it;
    int pos = r>>7, b = r&127;
    const float* x = X + (size_t)(pos*NB+b)*512 + dir*256;
    float acc[4][L];
    #pragma unroll
    for (int a=0;a<4;a++){
      #pragma unroll
      for (int l=0;l<L;l++) acc[a][l]=0.f;
    }
    float u=0.f;
    #pragma unroll
    for (int k=0;k<8;k++){
      int d = lane + k*32;
      float v = x[d];
      float v2 = v*v;
      u += v2;
      int rows[4] = {wrow0, wrow1, 4, 5};
      #pragma unroll
      for (int a=0;a<4;a++){
        const float* wr = &sw[rows[a]*L*D + d];
        #pragma unroll
        for (int l=0;l<L;l++) acc[a][l] += v2 * wr[l*D];
      }
    }
    #pragma unroll
    for (int off=16; off; off>>=1){
      u += __shfl_down_sync(0xffffffffu, u, off);
      #pragma unroll
      for (int a=0;a<4;a++){
        #pragma unroll
        for (int l=0;l<L;l++) acc[a][l] += __shfl_down_sync(0xffffffffu, acc[a][l], off);
      }
    }
    if (lane==0){
      float* o = dst + ((size_t)(dir*S + pos)*NB + b)*33;
      #pragma unroll
      for (int a=0;a<4;a++){
        #pragma unroll
        for (int l=0;l<L;l++) o[a*8+l] = sqrtf(acc[a][l]);
      }
      o[32] = sqrtf(u);
    }
  }
}

// ---------------- K_main: 9-channel diag-weighted GEMM via f32x2 ----------------
// grid (4 s-tiles, 128 b, 2 dir), block 256. Per CTA: 64 s x 256 t x 256 d x 9 ch.
// smem strides of 258 words keep 8B alignment + conflict-free LDS.64.
#define STRD 258
#define SM_MAIN ((80*STRD + 8*256 + 16*9 + 64*9)*4)

__global__ void __launch_bounds__(256) k_main(const float* __restrict__ P,
                                              const float* __restrict__ Q,
                                              float* __restrict__ out){
  extern __shared__ float sm[];
  float* sP  = sm;                 // [64][258]
  float* sQ  = sm + 64*STRD;       // [16][258]
  float* sW  = sm + 80*STRD;       // [8][256]  maxpool W^2 channels
  float* sQn = sW + 8*256;         // [16][9]
  float* sPn = sQn + 16*9;         // [64][9]  p norms: 0-7 maxpool, 8 unweighted

  int sTile = blockIdx.x, b = blockIdx.y, dir = blockIdx.z;
  int sBase = sTile*64;
  int tid = threadIdx.x;
  int tx = tid & 7, ty = tid >> 3;   // ty: 0..31
  int sl0 = ty*2;

  for (int i=tid;i<8*D;i+=256) sW[i] = g_w2[2+dir][0][i];
  { // P tile [64 s][256 d]
    int row = tid>>2, dOff=(tid&3)*64;
    const float4* src = (const float4*)(P + (size_t)((sBase+row)*NB + b)*512 + dir*256 + dOff);
    float2* dstp = (float2*)(sP + row*STRD + dOff);
    #pragma unroll
    for (int k=0;k<16;k++){
      float4 v = src[k];
      dstp[2*k+0]=make_float2(v.x,v.y); dstp[2*k+1]=make_float2(v.z,v.w);
    }
  }
  for (int i=tid;i<64*9;i+=256){
    int row=i/9, slot=i%9;
    sPn[i] = g_np[dir][sBase+row][b][(slot<8)?(8+slot):32];
  }

  float ml[2][8];
  #pragma unroll
  for (int si=0;si<2;si++){
    #pragma unroll
    for (int l=0;l<8;l++) ml[si][l] = -3.4e38f;
  }
  float rs[2] = {0.f,0.f};
  float bv[2] = {-3.4e38f,-3.4e38f};
  int   bi[2] = {0,0};

  const ull* pA = (const ull*)(sP + sl0*STRD);
  const ull* pB = (const ull*)(sP + (sl0+1)*STRD);
  const ull* wp = (const ull*)sW;

  for (int tt=0; tt<16; tt++){
    __syncthreads();
    int tBase = tt*16;
    { // Q tile [16 t][256 d]
      int row = tid>>4, dOff=(tid&15)*16;
      const float4* src = (const float4*)(Q + (size_t)((tBase+row)*NB + b)*512 + dir*256 + dOff);
      float2* dstq = (float2*)(sQ + row*STRD + dOff);
      #pragma unroll
      for (int k=0;k<4;k++){
        float4 v = src[k];
        dstq[2*k+0]=make_float2(v.x,v.y); dstq[2*k+1]=make_float2(v.z,v.w);
      }
    }
    if (tid < 16*9){
      int t=tid/9, k=tid%9;
      sQn[tid] = g_nq[dir][tBase+t][b][(k<8)?(8+k):32];
    }
    __syncthreads();

    ull acc[9][2][2];
    #pragma unroll
    for (int c=0;c<9;c++){
      #pragma unroll
      for(int si=0;si<2;si++){ acc[c][si][0]=0ULL; acc[c][si][1]=0ULL; }
    }
    const ull* q0p = (const ull*)(sQ + (tx*2+0)*STRD);
    const ull* q1p = (const ull*)(sQ + (tx*2+1)*STRD);
    #pragma unroll 4
    for (int d2=0; d2<128; d2++){
      ull p0 = pA[d2], p1 = pB[d2];
      ull q0 = q0p[d2], q1 = q1p[d2];
      ull r00,r01,r10,r11;
      MUL2(r00,p0,q0); MUL2(r01,p0,q1); MUL2(r10,p1,q0); MUL2(r11,p1,q1);
      ADD2(acc[8][0][0], acc[8][0][0], r00);
      ADD2(acc[8][0][1], acc[8][0][1], r01);
      ADD2(acc[8][1][0], acc[8][1][0], r10);
      ADD2(acc[8][1][1], acc[8][1][1], r11);
      #pragma unroll
      for (int c=0;c<8;c++){
        ull w = wp[c*128 + d2];
        FMA2(acc[c][0][0], r00, w, acc[c][0][0]);
        FMA2(acc[c][0][1], r01, w, acc[c][0][1]);
        FMA2(acc[c][1][0], r10, w, acc[c][1][0]);
        FMA2(acc[c][1][1], r11, w, acc[c][1][1]);
      }
    }
    // per-tile epilogue
    #pragma unroll
    for (int si=0;si<2;si++){
      const float* pn = sPn + (sl0+si)*9;
      float a2[2];
      #pragma unroll
      for (int j=0;j<2;j++){
        int tl = tx*2+j;
        #pragma unroll
        for (int l=0;l<8;l++){
          float lo,hi; UNPACK2(lo,hi,acc[l][si][j]);
          float v = (lo+hi) / fmaxf(pn[l]*sQn[tl*9+l], EPS);
          ml[si][l] = fmaxf(ml[si][l], v);
        }
        float lo,hi; UNPACK2(lo,hi,acc[8][si][j]);
        float al = (lo+hi) / fmaxf(pn[8]*sQn[tl*9+8], EPS);
        a2[j] = al;
        rs[si] += al;
        if (al > bv[si]){ bv[si]=al; bi[si]=tBase+tl; }
      }
      float2* ap = (float2*)&g_alpha[dir][b][sBase+sl0+si][tBase + tx*2];
      *ap = make_float2(a2[0],a2[1]);
    }
  }
  // reduce across tx (8 lanes share s rows)
  #pragma unroll
  for (int off=1; off<8; off<<=1){
    #pragma unroll
    for (int si=0;si<2;si++){
      rs[si] += __shfl_xor_sync(0xffffffffu, rs[si], off);
      float ov = __shfl_xor_sync(0xffffffffu, bv[si], off);
      int   oi = __shfl_xor_sync(0xffffffffu, bi[si], off);
      if (ov > bv[si] || (ov == bv[si] && oi < bi[si])){ bv[si]=ov; bi[si]=oi; }
      #pragma unroll
      for (int l=0;l<8;l++) ml[si][l] = fmaxf(ml[si][l], __shfl_xor_sync(0xffffffffu, ml[si][l], off));
    }
  }
  if (tx==0){
    #pragma unroll
    for (int si=0;si<2;si++){
      int sg = sBase + sl0 + si;
      g_rowsum[dir][b][sg] = rs[si];
      g_amax[dir][b][sg]   = bi[si];
      float* o = out + ((size_t)sg*NB + b)*64 + 16 + dir*8;
      #pragma unroll
      for (int l=0;l<8;l++) o[l] = ml[si][l];
    }
  }
}

// ---------------- K_hmean: h = (alpha @ Q) / rowsum, f32x2 over d ----------------
#define SM_H ((96*STRD)*4)

__global__ void __launch_bounds__(256) k_hmean(const float* __restrict__ Q){
  extern __shared__ float sm[];
  float* sA = sm;              // [64 s][258] (256 t)
  float* sQ = sm + 64*STRD;    // [32 t][258] (256 d)
  int sTile=blockIdx.x, b=blockIdx.y, dir=blockIdx.z;
  int sBase = sTile*64;
  int tid=threadIdx.x;
  int tx = tid & 15, ty = tid >> 4;
  {
    int row=tid>>2, tOff=(tid&3)*64;
    const float4* src=(const float4*)&g_alpha[dir][b][sBase+row][tOff];
    float2* dsta = (float2*)(sA + row*STRD + tOff);
    #pragma unroll
    for (int k=0;k<16;k++){
      float4 v=src[k];
      dsta[2*k+0]=make_float2(v.x,v.y); dsta[2*k+1]=make_float2(v.z,v.w);
    }
  }
  ull acc[4][8];
  #pragma unroll
  for (int i=0;i<4;i++){
    #pragma unroll
    for(int k2=0;k2<8;k2++) acc[i][k2]=0ULL;
  }
  for (int tt=0;tt<8;tt++){
    __syncthreads();
    int tBase=tt*32;
    {
      int row=tid>>3, dOff=(tid&7)*32;
      const float4* src=(const float4*)(Q + (size_t)((tBase+row)*NB+b)*512 + dir*256 + dOff);
      float2* dstq = (float2*)(sQ + row*STRD + dOff);
      #pragma unroll
      for (int k=0;k<8;k++){
        float4 v=src[k];
        dstq[2*k+0]=make_float2(v.x,v.y); dstq[2*k+1]=make_float2(v.z,v.w);
      }
    }
    __syncthreads();
    for (int t=0;t<32;t++){
      ull ap[4];
      #pragma unroll
      for (int i=0;i<4;i++){
        float a = sA[(ty*4+i)*STRD + tBase + t];
        PACK2(ap[i], a);
      }
      const float* qr = sQ + t*STRD + tx*2;
      #pragma unroll
      for (int k2=0;k2<8;k2++){
        ull qp = *(const ull*)(qr + 32*k2);
        #pragma unroll
        for (int i=0;i<4;i++) FMA2(acc[i][k2], ap[i], qp, acc[i][k2]);
      }
    }
  }
  #pragma unroll
  for (int i=0;i<4;i++){
    int sg = sBase + ty*4 + i;
    float inv = 1.0f / g_rowsum[dir][b][sg];
    float* o = &g_h[dir][b][sg][0];
    #pragma unroll
    for (int k2=0;k2<8;k2++){
      float lo,hi; UNPACK2(lo,hi,acc[i][k2]);
      *(float2*)(o + tx*2 + 32*k2) = make_float2(lo*inv, hi*inv);
    }
  }
}

// ---------------- K_epi: full-match, attentive, max-attentive ----------------
__global__ void __launch_bounds__(64) k_epi(const float* __restrict__ P,
                                            const float* __restrict__ Q,
                                            float* __restrict__ out){
  int s = blockIdx.x, b = blockIdx.y;
  int tid=threadIdx.x;
  int dir = tid>>5, lane = tid&31;
  const float* p  = P + (size_t)(s*NB+b)*512 + dir*256;
  int qpos = dir ? 0 : (S-1);
  const float* qf = Q + (size_t)(qpos*NB+b)*512 + dir*256;
  int ts = g_amax[dir][b][s];
  const float* qm = Q + (size_t)(ts*NB+b)*512 + dir*256;
  const float* h  = &g_h[dir][b][s][0];
  float aF[8], aA[8], aH[8], aM[8];
  #pragma unroll
  for (int l=0;l<8;l++){ aF[l]=0.f;aA[l]=0.f;aH[l]=0.f;aM[l]=0.f; }
  #pragma unroll
  for (int k=0;k<8;k++){
    int d = lane + 32*k;
    float pv=p[d], qv=qf[d], hv=h[d], mv=qm[d];
    float pq=pv*qv, ph=pv*hv, hh=hv*hv, pm=pv*mv;
    #pragma unroll
    for (int l=0;l<8;l++){
      aF[l] += pq*g_w2[dir][l][d];
      float w4 = g_w2[4][l][d];
      aA[l] += ph*w4;
      aH[l] += hh*w4;
      aM[l] += pm*g_w2[5][l][d];
    }
  }
  #pragma unroll
  for (int off=16; off; off>>=1){
    #pragma unroll
    for (int l=0;l<8;l++){
      aF[l]+=__shfl_down_sync(0xffffffffu,aF[l],off);
      aA[l]+=__shfl_down_sync(0xffffffffu,aA[l],off);
      aH[l]+=__shfl_down_sync(0xffffffffu,aH[l],off);
      aM[l]+=__shfl_down_sync(0xffffffffu,aM[l],off);
    }
  }
  if (lane==0){
    const float* np_ = &g_np[dir][s][b][0];
    const float* nqf = &g_nq[dir][qpos][b][0];
    const float* nqm = &g_nq[dir][ts][b][0];
    float* o = out + ((size_t)s*NB+b)*64;
    #pragma unroll
    for (int l=0;l<8;l++){
      o[0  + dir*8 + l] = aF[l] / fmaxf(np_[l]    * nqf[l],       EPS);
      o[32 + dir*8 + l] = aA[l] / fmaxf(np_[16+l] * sqrtf(aH[l]), EPS);
      o[48 + dir*8 + l] = aM[l] / fmaxf(np_[24+l] * nqm[24+l],    EPS);
    }
  }
}

extern "C" void kernel_launch(void* const* d_in, const int* in_sizes, int n_in,
                              void* d_out, int out_size){
  const float* P = (const float*)d_in[0];
  const float* Q = (const float*)d_in[1];
  const float* W = (const float*)d_in[2];
  float* out = (float*)d_out;

  cudaFuncSetAttribute(k_main,  cudaFuncAttributeMaxDynamicSharedMemorySize, SM_MAIN);
  cudaFuncSetAttribute(k_hmean, cudaFuncAttributeMaxDynamicSharedMemorySize, SM_H);

  k_w2<<<12, 1024>>>(W);
  k_norms<<<2048, 128>>>(P, Q);
  k_main<<<dim3(4, NB, 2), 256, SM_MAIN>>>(P, Q, out);
  k_hmean<<<dim3(4, NB, 2), 256, SM_H>>>(Q);
  k_epi<<<dim3(S, NB), 64>>>(P, Q, out);
}

// round 7
// speedup vs baseline: 1.5652x; 1.5652x over previous
#include <cuda_runtime.h>
#include <cuda_bf16.h>
#include <math.h>
#include <stdint.h>

#define S 256
#define NB 128
#define D 256
#define L 8
#define EPS 1e-8f
typedef unsigned long long ull;
typedef unsigned int uint;

#define FMA2(d_, a_, b_, c_) asm("fma.rn.f32x2 %0, %1, %2, %3;" : "=l"(d_) : "l"(a_), "l"(b_), "l"(c_))
#define PACK2(d_, x_) asm("mov.b64 %0, {%1, %1};" : "=l"(d_) : "f"(x_))
#define UNPACK2(lo_, hi_, p_) asm("mov.b64 {%0, %1}, %2;" : "=f"(lo_), "=f"(hi_) : "l"(p_))

#define LDX4(r, addr) \
  asm volatile("ldmatrix.sync.aligned.m8n8.x4.shared.b16 {%0,%1,%2,%3}, [%4];" \
    : "=r"((r)[0]),"=r"((r)[1]),"=r"((r)[2]),"=r"((r)[3]) : "r"(addr))

#define MMA16816(d, a, b0_, b1_) \
  asm volatile("mma.sync.aligned.m16n8k16.row.col.f32.bf16.bf16.f32 " \
    "{%0,%1,%2,%3}, {%4,%5,%6,%7}, {%8,%9}, {%0,%1,%2,%3};" \
    : "+f"((d)[0]),"+f"((d)[1]),"+f"((d)[2]),"+f"((d)[3]) \
    : "r"((a)[0]),"r"((a)[1]),"r"((a)[2]),"r"((a)[3]), "r"(b0_),"r"(b1_))

#define CVTPAIR(d_, hi_, lo_) \
  asm("cvt.rn.bf16x2.f32 %0, %1, %2;" : "=r"(d_) : "f"(hi_), "f"(lo_))

__device__ __forceinline__ uint32_t smem_u32(const void* p){
  uint32_t a;
  asm("{ .reg .u64 t; cvta.to.shared.u64 t, %1; cvt.u32.u64 %0, t; }" : "=r"(a) : "l"(p));
  return a;
}
__device__ __forceinline__ uint enc_f(float x){
  uint u = __float_as_uint(x);
  return (u & 0x80000000u) ? ~u : (u | 0x80000000u);
}
__device__ __forceinline__ float dec_f(uint u){
  return __uint_as_float((u & 0x80000000u) ? (u & 0x7FFFFFFFu) : ~u);
}

// ---- scratch ----
__device__ __align__(16) float g_w2[6][L][D];
__device__ __align__(16) float g_np[2][S][NB][33];
__device__ __align__(16) float g_nq[2][S][NB][33];
__device__ __align__(16) float g_alpha[2][NB][S][S];
__device__ __align__(16) float g_rowsum[2][NB][S];
__device__ __align__(16) ull   g_pack[2][NB][S];      // argmax: (enc(a)<<32)|~t
__device__ __align__(16) uint  g_mp[2][NB][S][L];     // maxpool, encoded floats
__device__ __align__(16) float g_h[2][NB][S][D];
__device__ __align__(16) __nv_bfloat16 g_qhi[2][NB][S][D];
__device__ __align__(16) __nv_bfloat16 g_qlo[2][NB][S][D];

// ---------------- K0: W^2 ----------------
__global__ void k_w2(const float* __restrict__ W){
  int i = blockIdx.x*blockDim.x + threadIdx.x;
  if (i < 6*L*D){ float w = W[i]; (&g_w2[0][0][0])[i] = w*w; }
}

// ---------------- k_init: zero atomically-combined outputs ----------------
__global__ void k_init(){
  int i = blockIdx.x*1024 + threadIdx.x;
  if (i < 2*NB*S*L) (&g_mp[0][0][0][0])[i] = 0u;
  if (i < 2*NB*S){
    (&g_pack[0][0][0])[i] = 0ULL;
    (&g_rowsum[0][0][0])[i] = 0.f;
  }
}

// ---------------- k_split: Q -> bf16 hi/lo ----------------
__global__ void __launch_bounds__(256) k_split(const float* __restrict__ Q){
  int b = blockIdx.y, dir = blockIdx.z;
  int tid = threadIdx.x;
  int t = blockIdx.x*32 + (tid>>3), d0 = (tid&7)*32;
  const float4* src = (const float4*)(Q + (size_t)(t*NB + b)*512 + dir*256 + d0);
  unsigned short hbuf[32], lbuf[32];
  #pragma unroll
  for (int k=0;k<8;k++){
    float4 v = src[k];
    float xs[4] = {v.x, v.y, v.z, v.w};
    #pragma unroll
    for (int j=0;j<4;j++){
      __nv_bfloat16 h = __float2bfloat16_rn(xs[j]);
      __nv_bfloat16 lo = __float2bfloat16_rn(xs[j] - __bfloat162float(h));
      hbuf[4*k+j] = __bfloat16_as_ushort(h);
      lbuf[4*k+j] = __bfloat16_as_ushort(lo);
    }
  }
  size_t qi = ((size_t)(dir*NB+b)*256 + t)*256 + d0;
  #pragma unroll
  for (int k=0;k<4;k++){
    ((uint4*)(&g_qhi[0][0][0][0] + qi))[k] = ((uint4*)hbuf)[k];
    ((uint4*)(&g_qlo[0][0][0][0] + qi))[k] = ((uint4*)lbuf)[k];
  }
}

// ---------------- K1: weighted norms ----------------
__global__ void __launch_bounds__(128) k_norms(const float* __restrict__ P,
                                               const float* __restrict__ Q){
  __shared__ float sw[6*L*D];
  int tid = threadIdx.x;
  for (int i=tid; i<6*L*D; i+=128) sw[i] = (&g_w2[0][0][0])[i];
  __syncthreads();
  int warp = tid>>5, lane = tid&31;
  int tensor = warp>>1, dir = warp&1;
  const float* X = tensor ? Q : P;
  float* dst = tensor ? &g_nq[0][0][0][0] : &g_np[0][0][0][0];
  int wrow0 = dir, wrow1 = 2+dir;
  for (int it=0; it<16; it++){
    int r = blockIdx.x*16 + it;
    int pos = r>>7, b = r&127;
    const float* x = X + (size_t)(pos*NB+b)*512 + dir*256;
    float acc[4][L];
    #pragma unroll
    for (int a=0;a<4;a++)
      #pragma unroll
      for (int l=0;l<L;l++) acc[a][l]=0.f;
    float u=0.f;
    #pragma unroll
    for (int k=0;k<8;k++){
      int d = lane + k*32;
      float v = x[d];
      float v2 = v*v;
      u += v2;
      int rows[4] = {wrow0, wrow1, 4, 5};
      #pragma unroll
      for (int a=0;a<4;a++){
        const float* wr = &sw[rows[a]*L*D + d];
        #pragma unroll
        for (int l=0;l<L;l++) acc[a][l] += v2 * wr[l*D];
      }
    }
    #pragma unroll
    for (int off=16; off; off>>=1){
      u += __shfl_down_sync(0xffffffffu, u, off);
      #pragma unroll
      for (int a=0;a<4;a++)
        #pragma unroll
        for (int l=0;l<L;l++) acc[a][l] += __shfl_down_sync(0xffffffffu, acc[a][l], off);
    }
    if (lane==0){
      float* o = dst + ((size_t)(dir*S + pos)*NB + b)*33;
      #pragma unroll
      for (int a=0;a<4;a++)
        #pragma unroll
        for (int l=0;l<L;l++) o[a*8+l] = sqrtf(acc[a][l]);
      o[32] = sqrtf(u);
    }
  }
}

// ---------------- k_main_mma: 9-channel GEMM via mma.sync bf16x3 ----------------
// grid(8 = 4 sTiles x 2 tHalves, 128 b, 2 dir), 256 threads (8 warps: 4s x 2t).
// CTA tile: 64 s x 128 t x 256 d x 9 ch. Pitch 528B (33 x 16B chunks, odd) ->
// conflict-free ldmatrix.
#define BPITCH 528
#define OFF_BHI 0
#define OFF_BLO 67584
#define OFF_AHI 135168
#define OFF_ALO 168960
#define OFF_W2S 202752
#define OFF_QNS 210944
#define OFF_PNS 215552
#define SM_MM   217856

__global__ void __launch_bounds__(256) k_main_mma(const float* __restrict__ P,
                                                  float* __restrict__ out){
  extern __shared__ char smem[];
  float* sW2 = (float*)(smem + OFF_W2S);   // [8][256]
  float* sQn = (float*)(smem + OFF_QNS);   // [9][128] inverse q norms (local t)
  float* sPn = (float*)(smem + OFF_PNS);   // [9][64]  inverse p norms (local s)

  int sTile = blockIdx.x >> 1, tHalf = blockIdx.x & 1;
  int b = blockIdx.y, dir = blockIdx.z;
  int sBase = sTile*64, tBase = tHalf*128;
  int tid = threadIdx.x, wid = tid>>5, lane = tid&31;
  int swS = (wid>>1)*16;   // warp s offset within CTA
  int twT = (wid&1)*64;    // warp t offset within CTA

  for (int i=tid;i<8*256;i+=256) sW2[i] = g_w2[2+dir][0][i];
  for (int i=tid;i<9*128;i+=256){
    int c=i>>7, t=i&127;
    sQn[i] = 1.0f / g_nq[dir][tBase+t][b][(c<8)?(8+c):32];
  }
  for (int i=tid;i<9*64;i+=256){
    int c=i/64, r=i%64;
    sPn[i] = 1.0f / g_np[dir][sBase+r][b][(c<8)?(8+c):32];
  }
  { // B tiles: q hi/lo [128 t][256 d] bf16, pitch 528B. Each (r,h) stages 128
    // bf16 = 256 bytes = 16 x uint4.  (R6 bug: only 8 chunks were copied.)
    int r = tid>>1, h = tid&1;
    size_t qi = ((size_t)(dir*NB+b)*256 + tBase + r)*256 + h*128;
    const uint4* shi = (const uint4*)(&g_qhi[0][0][0][0] + qi);
    const uint4* slo = (const uint4*)(&g_qlo[0][0][0][0] + qi);
    char* dh = smem + OFF_BHI + r*BPITCH + h*256;
    char* dl = smem + OFF_BLO + r*BPITCH + h*256;
    #pragma unroll
    for (int k=0;k<16;k++){
      *(uint4*)(dh + 16*k) = shi[k];
      *(uint4*)(dl + 16*k) = slo[k];
    }
  }
  // p tile into registers: row = tid>>2 (0..63), cols cb*64..+63
  float preg[64];
  int prow = tid>>2, pcb = tid&3;
  {
    const float4* src = (const float4*)(P + ((size_t)(sBase+prow)*NB + b)*512 + dir*256 + pcb*64);
    #pragma unroll
    for (int k=0;k<16;k++){
      float4 v = src[k];
      preg[4*k+0]=v.x; preg[4*k+1]=v.y; preg[4*k+2]=v.z; preg[4*k+3]=v.w;
    }
  }

  uint32_t aHb = smem_u32(smem + OFF_AHI);
  uint32_t aLb = smem_u32(smem + OFF_ALO);
  uint32_t bHb = smem_u32(smem + OFF_BHI);
  uint32_t bLb = smem_u32(smem + OFF_BLO);

  uint32_t arow = swS + (lane&15);
  uint32_t acolx = ((lane&16)?16:0);             // bytes
  uint32_t aoffH = aHb + arow*BPITCH + acolx;
  uint32_t aoffL = aLb + arow*BPITCH + acolx;
  uint32_t brow_b = (lane&7) + ((lane&16)>>1);   // + g*16 + twT later
  uint32_t bcolx = ((lane&8)?16:0);

  for (int c=0; c<9; c++){
    __syncthreads();  // previous channel done reading A
    { // build A = p * w2[c] (w=1 for c==8), split hi/lo bf16
      char* dh = smem + OFF_AHI + prow*BPITCH + pcb*128;
      char* dl = smem + OFF_ALO + prow*BPITCH + pcb*128;
      const float* wrow = sW2 + c*256 + pcb*64;
      #pragma unroll
      for (int j=0;j<16;j++){
        float a0,a1,a2,a3;
        if (c<8){
          a0 = preg[4*j+0]*wrow[4*j+0]; a1 = preg[4*j+1]*wrow[4*j+1];
          a2 = preg[4*j+2]*wrow[4*j+2]; a3 = preg[4*j+3]*wrow[4*j+3];
        } else {
          a0 = preg[4*j+0]; a1 = preg[4*j+1]; a2 = preg[4*j+2]; a3 = preg[4*j+3];
        }
        uint32_t h01, h23, l01, l23;
        CVTPAIR(h01, a1, a0);
        CVTPAIR(h23, a3, a2);
        float f0 = __uint_as_float(h01<<16), f1 = __uint_as_float(h01 & 0xFFFF0000u);
        float f2 = __uint_as_float(h23<<16), f3 = __uint_as_float(h23 & 0xFFFF0000u);
        CVTPAIR(l01, a1-f1, a0-f0);
        CVTPAIR(l23, a3-f3, a2-f2);
        *(uint2*)(dh + 8*j) = make_uint2(h01, h23);
        *(uint2*)(dl + 8*j) = make_uint2(l01, l23);
      }
    }
    __syncthreads();

    float acc[8][4];
    #pragma unroll
    for (int nt=0;nt<8;nt++){ acc[nt][0]=0.f;acc[nt][1]=0.f;acc[nt][2]=0.f;acc[nt][3]=0.f; }

    for (int kc=0; kc<16; kc++){
      uint32_t ah[4], al[4];
      LDX4(ah, aoffH + kc*32);
      LDX4(al, aoffL + kc*32);
      #pragma unroll
      for (int g=0; g<4; g++){
        uint32_t boff = (twT + g*16 + brow_b)*BPITCH + kc*32 + bcolx;
        uint32_t bh[4], bl[4];
        LDX4(bh, bHb + boff);
        LDX4(bl, bLb + boff);
        MMA16816(acc[2*g],   ah, bh[0], bh[1]);
        MMA16816(acc[2*g],   ah, bl[0], bl[1]);
        MMA16816(acc[2*g],   al, bh[0], bh[1]);
        MMA16816(acc[2*g+1], ah, bh[2], bh[3]);
        MMA16816(acc[2*g+1], ah, bl[2], bl[3]);
        MMA16816(acc[2*g+1], al, bh[2], bh[3]);
      }
    }

    // epilogue: thread holds rows r0 = swS+lane/4, r1 = r0+8;
    // cols twT + nt*8 + 2*(lane&3) + {0,1}
    int rl0 = swS + (lane>>2), rl1 = rl0 + 8;
    if (c < 8){
      float m0=-3.4e38f, m1=-3.4e38f;
      const float* qn = sQn + c*128;
      #pragma unroll
      for (int nt=0;nt<8;nt++){
        int col = twT + nt*8 + 2*(lane&3);
        float q0 = qn[col], q1 = qn[col+1];
        m0 = fmaxf(m0, fmaxf(acc[nt][0]*q0, acc[nt][1]*q1));
        m1 = fmaxf(m1, fmaxf(acc[nt][2]*q0, acc[nt][3]*q1));
      }
      #pragma unroll
      for (int off=1; off<4; off<<=1){
        m0 = fmaxf(m0, __shfl_xor_sync(0xffffffffu, m0, off));
        m1 = fmaxf(m1, __shfl_xor_sync(0xffffffffu, m1, off));
      }
      if ((lane&3)==0){
        atomicMax(&g_mp[dir][b][sBase+rl0][c], enc_f(m0 * sPn[c*64+rl0]));
        atomicMax(&g_mp[dir][b][sBase+rl1][c], enc_f(m1 * sPn[c*64+rl1]));
      }
    } else {
      float invp0 = sPn[8*64 + rl0], invp1 = sPn[8*64 + rl1];
      const float* qn = sQn + 8*128;
      float rs0=0.f, rs1=0.f, bv0=-3.4e38f, bv1=-3.4e38f;
      int bi0=0, bi1=0;
      int sg0 = sBase + rl0, sg1 = sBase + rl1;
      float* arow0 = &g_alpha[dir][b][sg0][tBase];
      float* arow1 = &g_alpha[dir][b][sg1][tBase];
      #pragma unroll
      for (int nt=0;nt<8;nt++){
        int col = twT + nt*8 + 2*(lane&3);
        float q0 = qn[col], q1 = qn[col+1];
        float a00 = acc[nt][0]*q0*invp0, a01 = acc[nt][1]*q1*invp0;
        float a10 = acc[nt][2]*q0*invp1, a11 = acc[nt][3]*q1*invp1;
        *(float2*)(arow0 + col) = make_float2(a00, a01);
        *(float2*)(arow1 + col) = make_float2(a10, a11);
        rs0 += a00 + a01; rs1 += a10 + a11;
        int tg = tBase + col;
        if (a00>bv0){bv0=a00;bi0=tg;}
        if (a01>bv0){bv0=a01;bi0=tg+1;}
        if (a10>bv1){bv1=a10;bi1=tg;}
        if (a11>bv1){bv1=a11;bi1=tg+1;}
      }
      #pragma unroll
      for (int off=1; off<4; off<<=1){
        rs0 += __shfl_xor_sync(0xffffffffu, rs0, off);
        rs1 += __shfl_xor_sync(0xffffffffu, rs1, off);
        float ov0 = __shfl_xor_sync(0xffffffffu, bv0, off);
        int   oi0 = __shfl_xor_sync(0xffffffffu, bi0, off);
        if (ov0>bv0 || (ov0==bv0 && oi0<bi0)){bv0=ov0;bi0=oi0;}
        float ov1 = __shfl_xor_sync(0xffffffffu, bv1, off);
        int   oi1 = __shfl_xor_sync(0xffffffffu, bi1, off);
        if (ov1>bv1 || (ov1==bv1 && oi1<bi1)){bv1=ov1;bi1=oi1;}
      }
      if ((lane&3)==0){
        atomicAdd(&g_rowsum[dir][b][sg0], rs0);
        atomicAdd(&g_rowsum[dir][b][sg1], rs1);
        atomicMax(&g_pack[dir][b][sg0], ((ull)enc_f(bv0)<<32) | (uint)(0xFFFFFFFFu - (uint)bi0));
        atomicMax(&g_pack[dir][b][sg1], ((ull)enc_f(bv1)<<32) | (uint)(0xFFFFFFFFu - (uint)bi1));
      }
    }
  }
}

// ---------------- K_hmean: h = (alpha @ Q)/rowsum, f32x2 ----------------
#define STRD 258
#define SM_H ((96*STRD)*4)

__global__ void __launch_bounds__(256) k_hmean(const float* __restrict__ Q){
  extern __shared__ float sm[];
  float* sA = sm;
  float* sQ = sm + 64*STRD;
  int sTile=blockIdx.x, b=blockIdx.y, dir=blockIdx.z;
  int sBase = sTile*64;
  int tid=threadIdx.x;
  int tx = tid & 15, ty = tid >> 4;
  {
    int row=tid>>2, tOff=(tid&3)*64;
    const float4* src=(const float4*)&g_alpha[dir][b][sBase+row][tOff];
    float2* dsta = (float2*)(sA + row*STRD + tOff);
    #pragma unroll
    for (int k=0;k<16;k++){
      float4 v=src[k];
      dsta[2*k+0]=make_float2(v.x,v.y); dsta[2*k+1]=make_float2(v.z,v.w);
    }
  }
  ull acc[4][8];
  #pragma unroll
  for (int i=0;i<4;i++)
    #pragma unroll
    for(int k2=0;k2<8;k2++) acc[i][k2]=0ULL;
  for (int tt=0;tt<8;tt++){
    __syncthreads();
    int tBase=tt*32;
    {
      int row=tid>>3, dOff=(tid&7)*32;
      const float4* src=(const float4*)(Q + (size_t)((tBase+row)*NB+b)*512 + dir*256 + dOff);
      float2* dstq = (float2*)(sQ + row*STRD + dOff);
      #pragma unroll
      for (int k=0;k<8;k++){
        float4 v=src[k];
        dstq[2*k+0]=make_float2(v.x,v.y); dstq[2*k+1]=make_float2(v.z,v.w);
      }
    }
    __syncthreads();
    for (int t=0;t<32;t++){
      ull ap[4];
      #pragma unroll
      for (int i=0;i<4;i++){ float a = sA[(ty*4+i)*STRD + tBase + t]; PACK2(ap[i], a); }
      const float* qr = sQ + t*STRD + tx*2;
      #pragma unroll
      for (int k2=0;k2<8;k2++){
        ull qp = *(const ull*)(qr + 32*k2);
        #pragma unroll
        for (int i=0;i<4;i++) FMA2(acc[i][k2], ap[i], qp, acc[i][k2]);
      }
    }
  }
  #pragma unroll
  for (int i=0;i<4;i++){
    int sg = sBase + ty*4 + i;
    float inv = 1.0f / g_rowsum[dir][b][sg];
    float* o = &g_h[dir][b][sg][0];
    #pragma unroll
    for (int k2=0;k2<8;k2++){
      float lo,hi; UNPACK2(lo,hi,acc[i][k2]);
      *(float2*)(o + tx*2 + 32*k2) = make_float2(lo*inv, hi*inv);
    }
  }
}

// ---------------- K_epi ----------------
__global__ void __launch_bounds__(64) k_epi(const float* __restrict__ P,
                                            const float* __restrict__ Q,
                                            float* __restrict__ out){
  int s = blockIdx.x, b = blockIdx.y;
  int tid=threadIdx.x;
  int dir = tid>>5, lane = tid&31;
  const float* p  = P + (size_t)(s*NB+b)*512 + dir*256;
  int qpos = dir ? 0 : (S-1);
  const float* qf = Q + (size_t)(qpos*NB+b)*512 + dir*256;
  ull key = g_pack[dir][b][s];
  int ts = (int)(0xFFFFFFFFu - (uint)(key & 0xFFFFFFFFu));
  const float* qm = Q + (size_t)(ts*NB+b)*512 + dir*256;
  const float* h  = &g_h[dir][b][s][0];
  float aF[8], aA[8], aH[8], aM[8];
  #pragma unroll
  for (int l=0;l<8;l++){ aF[l]=0.f;aA[l]=0.f;aH[l]=0.f;aM[l]=0.f; }
  #pragma unroll
  for (int k=0;k<8;k++){
    int d = lane + 32*k;
    float pv=p[d], qv=qf[d], hv=h[d], mv=qm[d];
    float pq=pv*qv, ph=pv*hv, hh=hv*hv, pm=pv*mv;
    #pragma unroll
    for (int l=0;l<8;l++){
      aF[l] += pq*g_w2[dir][l][d];
      float w4 = g_w2[4][l][d];
      aA[l] += ph*w4;
      aH[l] += hh*w4;
      aM[l] += pm*g_w2[5][l][d];
    }
  }
  #pragma unroll
  for (int off=16; off; off>>=1){
    #pragma unroll
    for (int l=0;l<8;l++){
      aF[l]+=__shfl_down_sync(0xffffffffu,aF[l],off);
      aA[l]+=__shfl_down_sync(0xffffffffu,aA[l],off);
      aH[l]+=__shfl_down_sync(0xffffffffu,aH[l],off);
      aM[l]+=__shfl_down_sync(0xffffffffu,aM[l],off);
    }
  }
  if (lane==0){
    const float* np_ = &g_np[dir][s][b][0];
    const float* nqf = &g_nq[dir][qpos][b][0];
    const float* nqm = &g_nq[dir][ts][b][0];
    float* o = out + ((size_t)s*NB+b)*64;
    #pragma unroll
    for (int l=0;l<8;l++){
      o[0  + dir*8 + l] = aF[l] / fmaxf(np_[l]    * nqf[l],       EPS);
      o[16 + dir*8 + l] = dec_f(g_mp[dir][b][s][l]);
      o[32 + dir*8 + l] = aA[l] / fmaxf(np_[16+l] * sqrtf(aH[l]), EPS);
      o[48 + dir*8 + l] = aM[l] / fmaxf(np_[24+l] * nqm[24+l],    EPS);
    }
  }
}

extern "C" void kernel_launch(void* const* d_in, const int* in_sizes, int n_in,
                              void* d_out, int out_size){
  const float* P = (const float*)d_in[0];
  const float* Q = (const float*)d_in[1];
  const float* W = (const float*)d_in[2];
  float* out = (float*)d_out;

  cudaFuncSetAttribute(k_main_mma, cudaFuncAttributeMaxDynamicSharedMemorySize, SM_MM);
  cudaFuncSetAttribute(k_hmean,    cudaFuncAttributeMaxDynamicSharedMemorySize, SM_H);

  k_w2<<<12, 1024>>>(W);
  k_init<<<512, 1024>>>();
  k_split<<<dim3(8, NB, 2), 256>>>(Q);
  k_norms<<<2048, 128>>>(P, Q);
  k_main_mma<<<dim3(8, NB, 2), 256, SM_MM>>>(P, out);
  k_hmean<<<dim3(4, NB, 2), 256, SM_H>>>(Q);
  k_epi<<<dim3(S, NB), 64>>>(P, Q, out);
}